// round 4
// baseline (speedup 1.0000x reference)
#include <cuda_runtime.h>
#include <math.h>

#define SEQ   2048
#define NQ    8
#define EMB   256
#define DIN   264     // EMB + HID
#define TAGS  50

// Scratch (no allocation allowed): projected gate inputs and hidden states.
__device__ float g_Xp[SEQ * 32];   // [t][g*8+w] = emb-part dot + b + theta
__device__ float g_H [SEQ * NQ];   // h_t

// ---------------------------------------------------------------------------
// Kernel A: Xp[t][g*8+w] = sum_{k<256} emb[sent[t]][k] * W_g[w][k] + b_g[w] + th_g[w]
// 2048 blocks x 256 threads; 8 threads per output dot.
// ---------------------------------------------------------------------------
__global__ void proj_kernel(const int* __restrict__ sent,
                            const float* __restrict__ emb,
                            const float* __restrict__ Wf, const float* __restrict__ bf, const float* __restrict__ thf,
                            const float* __restrict__ Wi, const float* __restrict__ bi, const float* __restrict__ thi,
                            const float* __restrict__ Wu, const float* __restrict__ bu, const float* __restrict__ thu,
                            const float* __restrict__ Wo, const float* __restrict__ bo, const float* __restrict__ tho)
{
    __shared__ float sx[EMB];
    const int t   = blockIdx.x;
    const int tid = threadIdx.x;
    const int row = sent[t];
    sx[tid] = emb[(size_t)row * EMB + tid];
    __syncthreads();

    const int out = tid >> 3;   // 0..31  (g*8+w)
    const int sub = tid & 7;
    const int g   = out >> 3;
    const int w   = out & 7;

    const float* W  = (g == 0) ? Wf  : (g == 1) ? Wi  : (g == 2) ? Wu  : Wo;
    const float* b  = (g == 0) ? bf  : (g == 1) ? bi  : (g == 2) ? bu  : bo;
    const float* th = (g == 0) ? thf : (g == 1) ? thi : (g == 2) ? thu : tho;

    const float* Wr = W + w * DIN + sub;
    float s = 0.f;
    #pragma unroll
    for (int j = 0; j < EMB / 8; j++)
        s = fmaf(sx[sub + 8 * j], __ldg(Wr + 8 * j), s);

    // reduce 8 partials within each aligned 8-lane group
    #pragma unroll
    for (int off = 4; off; off >>= 1)
        s += __shfl_down_sync(0xffffffffu, s, off, 8);

    if (sub == 0)
        g_Xp[t * 32 + out] = s + b[w] + th[w];
}

// ---------------------------------------------------------------------------
// Kernel B: sequential LSTM recurrence, 1 warp.
// lane = g*8 + w. Each lane owns one (gate, wire) output.
// Quantum layer == prefix products of cos(phi):
//   out[w>=1] = prod_{0..w} cos(phi_j),  out[0] = prod_{1..7} cos(phi_j)
// All lanes with the same w compute identical (c, h), so shfl(h, k) from
// any lane yields h[k].
// ---------------------------------------------------------------------------
__global__ void lstm_kernel(const float* __restrict__ Wf, const float* __restrict__ Wi,
                            const float* __restrict__ Wu, const float* __restrict__ Wo)
{
    const unsigned FULL = 0xffffffffu;
    const int lane = threadIdx.x;   // 0..31
    const int g = lane >> 3;
    const int w = lane & 7;

    const float* W = (g == 0) ? Wf : (g == 1) ? Wi : (g == 2) ? Wu : Wo;
    float wh[NQ];
    #pragma unroll
    for (int k = 0; k < NQ; k++)
        wh[k] = __ldg(W + w * DIN + EMB + k);   // recurrent weights

    float hreg = 0.f;   // h[w] (replicated across gate groups)
    float creg = 0.f;   // c[w]
    float ycur = __ldg(&g_Xp[lane]);

    #pragma unroll 1
    for (int t = 0; t < SEQ; t++) {
        // prefetch next step's projected input (independent of recurrence)
        float ynext = (t + 1 < SEQ) ? __ldg(&g_Xp[(t + 1) * 32 + lane]) : 0.f;

        // phi = Xp + h . wh
        float y = ycur;
        #pragma unroll
        for (int k = 0; k < NQ; k++) {
            float hk = __shfl_sync(FULL, hreg, k);
            y = fmaf(hk, wh[k], y);
        }

        float cw = __cosf(y);

        // all-gather the 8 cosines of this lane's gate (width-8 shfl)
        float cc[NQ];
        #pragma unroll
        for (int k = 0; k < NQ; k++)
            cc[k] = __shfl_sync(FULL, cw, k, 8);

        // predicated prefix product: ev = prod_{0..w}
        float ev = cc[0];
        if (w >= 1) ev *= cc[1];
        if (w >= 2) ev *= cc[2];
        if (w >= 3) ev *= cc[3];
        if (w >= 4) ev *= cc[4];
        if (w >= 5) ev *= cc[5];
        if (w >= 6) ev *= cc[6];
        if (w >= 7) ev *= cc[7];
        // wire 0: prod_{1..7} (balanced tree, off critical path of the chain)
        float q = (cc[1] * cc[2]) * (cc[3] * cc[4]);
        q *= (cc[5] * cc[6]) * cc[7];
        if (w == 0) ev = q;

        // activation: sigmoid for f,i,o; tanh (=2*sigmoid(2x)-1) for u (g==2)
        float xarg = (g == 2) ? (-2.f * ev) : (-ev);
        float e    = __expf(xarg);
        float sgm  = __fdividef(1.f, 1.f + e);
        float a    = (g == 2) ? fmaf(2.f, sgm, -1.f) : sgm;

        // cross-gate gather at wire w
        float fv = __shfl_sync(FULL, a, w);
        float iv = __shfl_sync(FULL, a, w + 8);
        float gv = __shfl_sync(FULL, a, w + 16);
        float ov = __shfl_sync(FULL, a, w + 24);

        // state update (identical across the 4 gate groups)
        float cn = fmaf(fv, creg, iv * gv);
        creg = cn;
        float e2  = __expf(-2.f * cn);
        float tnh = fmaf(-2.f, __fdividef(e2, 1.f + e2), 1.f);  // (1-e2)/(1+e2)
        hreg = ov * tnh;

        if (lane < NQ)
            g_H[t * NQ + lane] = hreg;

        ycur = ynext;
    }
}

// ---------------------------------------------------------------------------
// Kernel C: logits = H @ Wt^T + bt, then log_softmax over 50 tags.
// 2048 blocks x 32 threads; lane handles tags (lane, lane+32).
// ---------------------------------------------------------------------------
__global__ void head_kernel(const float* __restrict__ Wt, const float* __restrict__ bt,
                            float* __restrict__ out)
{
    const unsigned FULL = 0xffffffffu;
    const int t    = blockIdx.x;
    const int lane = threadIdx.x;

    float h[NQ];
    #pragma unroll
    for (int k = 0; k < NQ; k++)
        h[k] = g_H[t * NQ + k];

    const int j0 = lane;
    const int j1 = lane + 32;

    float l0;
    {
        float s = bt[j0];
        #pragma unroll
        for (int k = 0; k < NQ; k++)
            s = fmaf(h[k], __ldg(Wt + j0 * NQ + k), s);
        l0 = s;                       // j0 < 32 < 50 always valid
    }
    float l1 = -1e30f;
    if (j1 < TAGS) {
        float s = bt[j1];
        #pragma unroll
        for (int k = 0; k < NQ; k++)
            s = fmaf(h[k], __ldg(Wt + j1 * NQ + k), s);
        l1 = s;
    }

    float m = fmaxf(l0, l1);
    #pragma unroll
    for (int off = 16; off; off >>= 1)
        m = fmaxf(m, __shfl_xor_sync(FULL, m, off));

    float se = __expf(l0 - m) + ((j1 < TAGS) ? __expf(l1 - m) : 0.f);
    #pragma unroll
    for (int off = 16; off; off >>= 1)
        se += __shfl_xor_sync(FULL, se, off);

    float lse = m + logf(se);
    out[t * TAGS + j0] = l0 - lse;
    if (j1 < TAGS)
        out[t * TAGS + j1] = l1 - lse;
}

// ---------------------------------------------------------------------------
extern "C" void kernel_launch(void* const* d_in, const int* in_sizes, int n_in,
                              void* d_out, int out_size)
{
    const int*   sent = (const int*)  d_in[0];
    const float* emb  = (const float*)d_in[1];
    const float* Wf   = (const float*)d_in[2];
    const float* bf   = (const float*)d_in[3];
    const float* Wi   = (const float*)d_in[4];
    const float* bi   = (const float*)d_in[5];
    const float* Wu   = (const float*)d_in[6];
    const float* bu   = (const float*)d_in[7];
    const float* Wo   = (const float*)d_in[8];
    const float* bo   = (const float*)d_in[9];
    const float* thf  = (const float*)d_in[10];
    const float* thi  = (const float*)d_in[11];
    const float* thu  = (const float*)d_in[12];
    const float* tho  = (const float*)d_in[13];
    const float* Wt   = (const float*)d_in[14];
    const float* bt   = (const float*)d_in[15];
    float* out = (float*)d_out;

    proj_kernel<<<SEQ, 256>>>(sent, emb,
                              Wf, bf, thf,
                              Wi, bi, thi,
                              Wu, bu, thu,
                              Wo, bo, tho);
    lstm_kernel<<<1, 32>>>(Wf, Wi, Wu, Wo);
    head_kernel<<<SEQ, 32>>>(Wt, bt, out);
}